// round 8
// baseline (speedup 1.0000x reference)
#include <cuda_runtime.h>
#include <cuda_bf16.h>

// CenterLoss collapses analytically:
//   loss = ( sum_i clip(||x_i - c_{l_i}||^2, 1e-12, 1e12) + B*(C-1)*1e-12 ) / B
// Single kernel, single launch, 8 blocks x 1024 threads. Per-warp squared
// distances -> per-block combine (warp-0 shuffle tree over smem) -> ONE packed
// global atomic per block (8 total): bits [0,48) = fixed-point (2^24) sum,
// bits [48,64) = block counter. The block whose atomicAdd return shows
// count==BLOCKS-1 owns the full sum (old + own contribution). No fences,
// no second phase -- the sum travels inside the atomic value itself.

#define B_ROWS 1024
#define D_DIM  256
#define C_CLS  100000

#define RPW     4                         // rows per warp
#define WARPS   32
#define THREADS (WARPS * 32)              // 1024
#define BLOCKS  (B_ROWS / (WARPS * RPW))  // 8

#define FP_SCALE_F 16777216.0f            // 2^24
#define FP_SCALE_D 16777216.0
#define CNT_SHIFT  48
#define SUM_MASK   ((1ULL << CNT_SHIFT) - 1ULL)

static __device__ unsigned long long g_acc = 0;  // sum + counter, self-resetting

__global__ void __launch_bounds__(THREADS)
center_loss_kernel(const float* __restrict__ x,
                   const void*  __restrict__ labels_raw,
                   const float* __restrict__ centers,
                   float* __restrict__ out) {
    const int tid  = threadIdx.x;
    const int lane = tid & 31;
    const int warp = tid >> 5;
    const int base = (blockIdx.x * WARPS + warp) * RPW;   // first row of this warp

    const int*       p32 = (const int*)labels_raw;
    const long long* p64 = (const long long*)labels_raw;

    // Speculative int32 label loads (actual dtype; issued in parallel with
    // the detection loads so the fast path costs no extra round trip).
    int lab32[RPW];
    #pragma unroll
    for (int r = 0; r < RPW; r++) lab32[r] = p32[base + r];

    // Dtype detection: first 32B viewed as 4 int64. Genuine int64 labels are
    // all in [0, C); int32 data viewed as int64 is lo|hi<<32 >= 2^32 unless
    // hi==0 -- four consecutive zero labels is effectively impossible.
    bool is64 = true;
    #pragma unroll
    for (int i = 0; i < 4; i++) {
        long long v = p64[i];
        if (v < 0 || v >= (long long)C_CLS) is64 = false;
    }

    long long lab[RPW];
    #pragma unroll
    for (int r = 0; r < RPW; r++) {
        long long l = is64 ? p64[base + r] : (long long)lab32[r];
        if (l < 0) l = 0;                       // never OOB even if detection wrong
        if (l >= C_CLS) l = C_CLS - 1;
        lab[r] = l;
    }

    // Gather: 4 rows x (2 float4 from x + 2 float4 from centers) per lane
    // = 16 independent LDG.128 in flight.
    float4 xa[RPW][2], ca[RPW][2];
    #pragma unroll
    for (int r = 0; r < RPW; r++) {
        const float4* xr = (const float4*)(x + (size_t)(base + r) * D_DIM);
        const float4* cr = (const float4*)(centers + (size_t)lab[r] * D_DIM);
        xa[r][0] = xr[lane];       xa[r][1] = xr[lane + 32];
        ca[r][0] = cr[lane];       ca[r][1] = cr[lane + 32];
    }

    // Per-row squared distance + warp reduction (4 independent trees, ILP).
    float s[RPW];
    #pragma unroll
    for (int r = 0; r < RPW; r++) {
        float d0 = xa[r][0].x - ca[r][0].x, d1 = xa[r][0].y - ca[r][0].y;
        float d2 = xa[r][0].z - ca[r][0].z, d3 = xa[r][0].w - ca[r][0].w;
        float e0 = xa[r][1].x - ca[r][1].x, e1 = xa[r][1].y - ca[r][1].y;
        float e2 = xa[r][1].z - ca[r][1].z, e3 = xa[r][1].w - ca[r][1].w;
        s[r] = d0*d0 + d1*d1 + d2*d2 + d3*d3
             + e0*e0 + e1*e1 + e2*e2 + e3*e3;
    }
    #pragma unroll
    for (int off = 16; off > 0; off >>= 1) {
        #pragma unroll
        for (int r = 0; r < RPW; r++)
            s[r] += __shfl_xor_sync(0xFFFFFFFFu, s[r], off);
    }

    // Per-warp quantize (clamp per row first, faithful to the reference).
    __shared__ unsigned long long s_q[WARPS];
    if (lane == 0) {
        unsigned long long q = 0;
        #pragma unroll
        for (int r = 0; r < RPW; r++) {
            float v = fminf(fmaxf(s[r], 1e-12f), 1e12f);
            q += __float2ull_rn(v * FP_SCALE_F);
        }
        s_q[warp] = q;
    }
    __syncthreads();

    // Block combine: warp 0 loads the 32 per-warp values and shuffle-reduces
    // them in parallel (exact integer adds, deterministic), then ONE packed
    // global atomic per block. The returned old value is the synchronization:
    // count==BLOCKS-1 means every other block's add has already landed.
    if (warp == 0) {
        unsigned long long q = s_q[lane];
        #pragma unroll
        for (int off = 16; off > 0; off >>= 1)
            q += __shfl_xor_sync(0xFFFFFFFFu, q, off);

        if (lane == 0) {
            unsigned long long contrib = (1ULL << CNT_SHIFT) + q;
            unsigned long long old = atomicAdd(&g_acc, contrib);
            if ((old >> CNT_SHIFT) == (unsigned long long)(BLOCKS - 1)) {
                unsigned long long tot = (old + contrib) & SUM_MASK;
                const double floor_term = (double)B_ROWS * (double)(C_CLS - 1) * 1e-12;
                double sum = (double)tot / FP_SCALE_D;
                out[0] = (float)((sum + floor_term) / (double)B_ROWS);
                atomicExch(&g_acc, 0ULL);       // reset for next graph replay
            }
        }
    }
}

extern "C" void kernel_launch(void* const* d_in, const int* in_sizes, int n_in,
                              void* d_out, int out_size) {
    // Identify inputs by element count (robust to ordering):
    //   x: 262144, labels: 1024, centers: 25600000
    const float* x       = nullptr;
    const void*  labels  = nullptr;
    const float* centers = nullptr;
    for (int i = 0; i < n_in; i++) {
        if (in_sizes[i] == B_ROWS * D_DIM)      x       = (const float*)d_in[i];
        else if (in_sizes[i] == B_ROWS)         labels  = d_in[i];
        else if (in_sizes[i] == C_CLS * D_DIM)  centers = (const float*)d_in[i];
    }
    float* out = (float*)d_out;

    center_loss_kernel<<<BLOCKS, THREADS>>>(x, labels, centers, out);
}

// round 9
// speedup vs baseline: 1.0332x; 1.0332x over previous
#include <cuda_runtime.h>
#include <cuda_bf16.h>

// CenterLoss collapses analytically:
//   loss = ( sum_i clip(||x_i - c_{l_i}||^2, 1e-12, 1e12) + B*(C-1)*1e-12 ) / B
// Single kernel, single launch, 32 blocks x 256 threads (R7 shape -- R8 showed
// that concentrating the gather onto few SMs blows up the L1tex queue).
// Two-level packed counter+sum protocol, fence-free and deterministic:
//   level 1 (smem):  each warp's lane 0 atomicAdds (1<<48)+q_warp to a shared
//                    word; the warp seeing count==WARPS-1 owns the block sum.
//   level 2 (gmem):  that warp atomicAdds (1<<48)+q_block to g_acc; the block
//                    seeing count==BLOCKS-1 owns the full sum and writes out.
// No end-of-block barrier: the last-finishing warp flows straight from its
// ATOMS return value into the global ATOMG.

#define B_ROWS 1024
#define D_DIM  256
#define C_CLS  100000

#define RPW     4                         // rows per warp
#define WARPS   8
#define THREADS (WARPS * 32)              // 256
#define BLOCKS  (B_ROWS / (WARPS * RPW))  // 32

#define FP_SCALE_F 16777216.0f            // 2^24
#define FP_SCALE_D 16777216.0
#define CNT_SHIFT  48
#define SUM_MASK   ((1ULL << CNT_SHIFT) - 1ULL)

static __device__ unsigned long long g_acc = 0;  // sum + counter, self-resetting

__global__ void __launch_bounds__(THREADS)
center_loss_kernel(const float* __restrict__ x,
                   const void*  __restrict__ labels_raw,
                   const float* __restrict__ centers,
                   float* __restrict__ out) {
    const int tid  = threadIdx.x;
    const int lane = tid & 31;
    const int warp = tid >> 5;
    const int base = (blockIdx.x * WARPS + warp) * RPW;   // first row of this warp

    // smem packed accumulator init -- barrier sits at the TOP, before any
    // long-latency work, so all warps arrive within a few cycles.
    __shared__ unsigned long long s_pack;
    if (tid == 0) s_pack = 0ULL;
    __syncthreads();

    const int*       p32 = (const int*)labels_raw;
    const long long* p64 = (const long long*)labels_raw;

    // Speculative int32 label loads (actual dtype; issued in parallel with
    // the detection loads so the fast path costs no extra round trip).
    int lab32[RPW];
    #pragma unroll
    for (int r = 0; r < RPW; r++) lab32[r] = p32[base + r];

    // Dtype detection: first 32B viewed as 4 int64. Genuine int64 labels are
    // all in [0, C); int32 data viewed as int64 is lo|hi<<32 >= 2^32 unless
    // hi==0 -- four consecutive zero labels is effectively impossible.
    bool is64 = true;
    #pragma unroll
    for (int i = 0; i < 4; i++) {
        long long v = p64[i];
        if (v < 0 || v >= (long long)C_CLS) is64 = false;
    }

    long long lab[RPW];
    #pragma unroll
    for (int r = 0; r < RPW; r++) {
        long long l = is64 ? p64[base + r] : (long long)lab32[r];
        if (l < 0) l = 0;                       // never OOB even if detection wrong
        if (l >= C_CLS) l = C_CLS - 1;
        lab[r] = l;
    }

    // Gather: 4 rows x (2 float4 from x + 2 float4 from centers) per lane
    // = 16 independent LDG.128 in flight.
    float4 xa[RPW][2], ca[RPW][2];
    #pragma unroll
    for (int r = 0; r < RPW; r++) {
        const float4* xr = (const float4*)(x + (size_t)(base + r) * D_DIM);
        const float4* cr = (const float4*)(centers + (size_t)lab[r] * D_DIM);
        xa[r][0] = xr[lane];       xa[r][1] = xr[lane + 32];
        ca[r][0] = cr[lane];       ca[r][1] = cr[lane + 32];
    }

    // Per-row squared distance + warp reduction (4 independent trees, ILP).
    float s[RPW];
    #pragma unroll
    for (int r = 0; r < RPW; r++) {
        float d0 = xa[r][0].x - ca[r][0].x, d1 = xa[r][0].y - ca[r][0].y;
        float d2 = xa[r][0].z - ca[r][0].z, d3 = xa[r][0].w - ca[r][0].w;
        float e0 = xa[r][1].x - ca[r][1].x, e1 = xa[r][1].y - ca[r][1].y;
        float e2 = xa[r][1].z - ca[r][1].z, e3 = xa[r][1].w - ca[r][1].w;
        s[r] = d0*d0 + d1*d1 + d2*d2 + d3*d3
             + e0*e0 + e1*e1 + e2*e2 + e3*e3;
    }
    #pragma unroll
    for (int off = 16; off > 0; off >>= 1) {
        #pragma unroll
        for (int r = 0; r < RPW; r++)
            s[r] += __shfl_xor_sync(0xFFFFFFFFu, s[r], off);
    }

    // Lane 0 of each warp: clamp per row (faithful to the reference),
    // quantize, then level-1 smem packed atomic. The warp that sees
    // count==WARPS-1 owns the complete block sum and immediately issues
    // the level-2 global packed atomic.
    if (lane == 0) {
        unsigned long long q = 0;
        #pragma unroll
        for (int r = 0; r < RPW; r++) {
            float v = fminf(fmaxf(s[r], 1e-12f), 1e12f);
            q += __float2ull_rn(v * FP_SCALE_F);
        }

        unsigned long long wcontrib = (1ULL << CNT_SHIFT) + q;
        unsigned long long wold = atomicAdd(&s_pack, wcontrib);
        if ((wold >> CNT_SHIFT) == (unsigned long long)(WARPS - 1)) {
            unsigned long long qblk = (wold + wcontrib) & SUM_MASK;

            unsigned long long contrib = (1ULL << CNT_SHIFT) + qblk;
            unsigned long long old = atomicAdd(&g_acc, contrib);
            if ((old >> CNT_SHIFT) == (unsigned long long)(BLOCKS - 1)) {
                unsigned long long tot = (old + contrib) & SUM_MASK;
                const double floor_term = (double)B_ROWS * (double)(C_CLS - 1) * 1e-12;
                double sum = (double)tot / FP_SCALE_D;
                out[0] = (float)((sum + floor_term) / (double)B_ROWS);
                atomicExch(&g_acc, 0ULL);       // reset for next graph replay
            }
        }
    }
}

extern "C" void kernel_launch(void* const* d_in, const int* in_sizes, int n_in,
                              void* d_out, int out_size) {
    // Identify inputs by element count (robust to ordering):
    //   x: 262144, labels: 1024, centers: 25600000
    const float* x       = nullptr;
    const void*  labels  = nullptr;
    const float* centers = nullptr;
    for (int i = 0; i < n_in; i++) {
        if (in_sizes[i] == B_ROWS * D_DIM)      x       = (const float*)d_in[i];
        else if (in_sizes[i] == B_ROWS)         labels  = d_in[i];
        else if (in_sizes[i] == C_CLS * D_DIM)  centers = (const float*)d_in[i];
    }
    float* out = (float*)d_out;

    center_loss_kernel<<<BLOCKS, THREADS>>>(x, labels, centers, out);
}

// round 10
// speedup vs baseline: 1.3527x; 1.3092x over previous
#include <cuda_runtime.h>
#include <cuda_bf16.h>

// CenterLoss collapses analytically:
//   loss = ( sum_i clip(||x_i - c_{l_i}||^2, 1e-12, 1e12) + B*(C-1)*1e-12 ) / B
// Single kernel, single launch, 32 blocks x 256 threads (the R7 shape --
// R8 showed concentrating the gather onto few SMs regresses; R9 showed the
// smem-ATOMS completion protocol regresses vs STS+syncthreads+combine).
// Per-warp squared distances -> per-block smem integer combine -> ONE packed
// global atomic per block (32 total): bits [0,48) = fixed-point (2^24) sum,
// bits [48,64) = block counter. The block whose atomicAdd return shows
// count==BLOCKS-1 owns the full sum (old + own contribution). No fences,
// no second phase -- the sum travels inside the atomic value itself.
// Reset is a PLAIN store: when count==BLOCKS-1 every other add has landed
// and nothing else touches g_acc this launch.

#define B_ROWS 1024
#define D_DIM  256
#define C_CLS  100000

#define RPW     4                         // rows per warp
#define WARPS   8
#define THREADS (WARPS * 32)              // 256
#define BLOCKS  (B_ROWS / (WARPS * RPW))  // 32

#define FP_SCALE_F 16777216.0f            // 2^24
#define FP_SCALE_D 16777216.0
#define CNT_SHIFT  48
#define SUM_MASK   ((1ULL << CNT_SHIFT) - 1ULL)

static __device__ unsigned long long g_acc = 0;  // sum + counter, self-resetting

__global__ void __launch_bounds__(THREADS)
center_loss_kernel(const float* __restrict__ x,
                   const void*  __restrict__ labels_raw,
                   const float* __restrict__ centers,
                   float* __restrict__ out) {
    const int tid  = threadIdx.x;
    const int lane = tid & 31;
    const int warp = tid >> 5;
    const int base = (blockIdx.x * WARPS + warp) * RPW;   // first row of this warp

    const int*       p32 = (const int*)labels_raw;
    const long long* p64 = (const long long*)labels_raw;

    // Speculative int32 label loads (actual dtype; issued in parallel with
    // the detection loads so the fast path costs no extra round trip).
    int lab32[RPW];
    #pragma unroll
    for (int r = 0; r < RPW; r++) lab32[r] = p32[base + r];

    // Dtype detection: first 32B viewed as 4 int64. Genuine int64 labels are
    // all in [0, C); int32 data viewed as int64 is lo|hi<<32 >= 2^32 unless
    // hi==0 -- four consecutive zero labels is effectively impossible.
    bool is64 = true;
    #pragma unroll
    for (int i = 0; i < 4; i++) {
        long long v = p64[i];
        if (v < 0 || v >= (long long)C_CLS) is64 = false;
    }

    long long lab[RPW];
    #pragma unroll
    for (int r = 0; r < RPW; r++) {
        long long l = is64 ? p64[base + r] : (long long)lab32[r];
        if (l < 0) l = 0;                       // never OOB even if detection wrong
        if (l >= C_CLS) l = C_CLS - 1;
        lab[r] = l;
    }

    // Gather: 4 rows x (2 float4 from x + 2 float4 from centers) per lane
    // = 16 independent LDG.128 in flight.
    float4 xa[RPW][2], ca[RPW][2];
    #pragma unroll
    for (int r = 0; r < RPW; r++) {
        const float4* xr = (const float4*)(x + (size_t)(base + r) * D_DIM);
        const float4* cr = (const float4*)(centers + (size_t)lab[r] * D_DIM);
        xa[r][0] = xr[lane];       xa[r][1] = xr[lane + 32];
        ca[r][0] = cr[lane];       ca[r][1] = cr[lane + 32];
    }

    // Per-row squared distance + warp reduction (4 independent trees, ILP).
    float s[RPW];
    #pragma unroll
    for (int r = 0; r < RPW; r++) {
        float d0 = xa[r][0].x - ca[r][0].x, d1 = xa[r][0].y - ca[r][0].y;
        float d2 = xa[r][0].z - ca[r][0].z, d3 = xa[r][0].w - ca[r][0].w;
        float e0 = xa[r][1].x - ca[r][1].x, e1 = xa[r][1].y - ca[r][1].y;
        float e2 = xa[r][1].z - ca[r][1].z, e3 = xa[r][1].w - ca[r][1].w;
        s[r] = d0*d0 + d1*d1 + d2*d2 + d3*d3
             + e0*e0 + e1*e1 + e2*e2 + e3*e3;
    }
    #pragma unroll
    for (int off = 16; off > 0; off >>= 1) {
        #pragma unroll
        for (int r = 0; r < RPW; r++)
            s[r] += __shfl_xor_sync(0xFFFFFFFFu, s[r], off);
    }

    // Per-warp quantize (clamp per row first, faithful to the reference).
    __shared__ unsigned long long s_q[WARPS];
    if (lane == 0) {
        unsigned long long q = 0;
        #pragma unroll
        for (int r = 0; r < RPW; r++) {
            float v = fminf(fmaxf(s[r], 1e-12f), 1e12f);
            q += __float2ull_rn(v * FP_SCALE_F);
        }
        s_q[warp] = q;
    }
    __syncthreads();

    // ONE packed global atomic per block. The returned old value is the
    // synchronization: count==BLOCKS-1 means every other block's add landed.
    if (tid == 0) {
        unsigned long long q = 0;
        #pragma unroll
        for (int w = 0; w < WARPS; w++) q += s_q[w];   // exact integer adds

        unsigned long long contrib = (1ULL << CNT_SHIFT) + q;
        unsigned long long old = atomicAdd(&g_acc, contrib);
        if ((old >> CNT_SHIFT) == (unsigned long long)(BLOCKS - 1)) {
            unsigned long long tot = (old + contrib) & SUM_MASK;
            const double floor_term = (double)B_ROWS * (double)(C_CLS - 1) * 1e-12;
            double sum = (double)tot / FP_SCALE_D;
            out[0] = (float)((sum + floor_term) / (double)B_ROWS);
            g_acc = 0ULL;   // plain store: no contenders remain this launch;
                            // launch boundary orders it before the next replay
        }
    }
}

extern "C" void kernel_launch(void* const* d_in, const int* in_sizes, int n_in,
                              void* d_out, int out_size) {
    // Identify inputs by element count (robust to ordering):
    //   x: 262144, labels: 1024, centers: 25600000
    const float* x       = nullptr;
    const void*  labels  = nullptr;
    const float* centers = nullptr;
    for (int i = 0; i < n_in; i++) {
        if (in_sizes[i] == B_ROWS * D_DIM)      x       = (const float*)d_in[i];
        else if (in_sizes[i] == B_ROWS)         labels  = d_in[i];
        else if (in_sizes[i] == C_CLS * D_DIM)  centers = (const float*)d_in[i];
    }
    float* out = (float*)d_out;

    center_loss_kernel<<<BLOCKS, THREADS>>>(x, labels, centers, out);
}